// round 17
// baseline (speedup 1.0000x reference)
#include <cuda_runtime.h>
#include <math.h>

#define Dm   768
#define Hn   12
#define HS   64
#define Ln   12
#define Tt   1024
#define Bb   4
#define Vv   50257
#define NP   50304           // lm_W padded stride (multiple of 128)
#define MR   4096            // B*T rows
#define FF   3072
#define EPSL 1e-5f

#define BM 128
#define BN 128
#define BK 16
#define GT 128               // gemm threads (4 warps, 2x2 of 64x64 warp tiles)

// fragment-layout SMEM strides (in unsigned words)
#define A_KBLK 1028          // 8 mtiles * 128 + 4 pad
#define A_BUF  2056          // 2 kblks
#define B_NT   66            // 32 lanes * 2 + 2 pad
#define B_KBLK 1058          // 16 ntiles * 66 + 2 pad
#define B_BUF  2116          // 2 kblks

#define FA_PAD 68

// ---------------- scratch (static device globals; no runtime alloc) ----------
__device__ float g_x[MR * Dm];
__device__ float g_h[MR * Dm];
__device__ float g_q[MR * Dm];
__device__ float g_k[MR * Dm];
__device__ float g_v[MR * Dm];
__device__ float g_ao[MR * Dm];
__device__ float g_mlp[MR * FF];
__device__ float g_lmWp[(size_t)Dm * NP];        // padded+rounded lm_W
__device__ float g_wq[(size_t)Ln * Dm * Dm];     // tf32-rounded weights
__device__ float g_wk[(size_t)Ln * Dm * Dm];
__device__ float g_wv[(size_t)Ln * Dm * Dm];
__device__ float g_wo[(size_t)Ln * Dm * Dm];
__device__ float g_w1[(size_t)Ln * Dm * FF];
__device__ float g_w2[(size_t)Ln * FF * Dm];
__device__ float g_nll[MR];

// ---------------- tf32 rounding helper ---------------------------------------
__device__ __forceinline__ unsigned f2tf(float f) {
    unsigned r;
    asm("cvt.rna.tf32.f32 %0, %1;" : "=r"(r) : "f"(f));
    return r;
}
__device__ __forceinline__ float roundtf(float f) {
    return __uint_as_float(f2tf(f));
}

// ---------------- prep: tf32-round copy (grid-stride) -------------------------
__global__ void round_copy(const float* __restrict__ src, float* __restrict__ dst,
                           size_t n) {
    for (size_t i = (size_t)blockIdx.x * blockDim.x + threadIdx.x; i < n;
         i += (size_t)gridDim.x * blockDim.x)
        dst[i] = roundtf(src[i]);
}

// ---------------- pad + round lm_W into stride-NP buffer ----------------------
__global__ void pad_lmW(const float* __restrict__ w, float* __restrict__ wp) {
    int k = blockIdx.x;                                  // 0..767
    const float* src = w + (size_t)k * Vv;
    float* dst = wp + (size_t)k * NP;
    for (int j = threadIdx.x; j < NP; j += blockDim.x)
        dst[j] = (j < Vv) ? roundtf(src[j]) : 0.0f;
}

// ---------------- embedding --------------------------------------------------
__global__ void embed_kernel(const int* __restrict__ idx,
                             const float* __restrict__ tok,
                             const float* __restrict__ pos,
                             float* __restrict__ x) {
    int row = blockIdx.x;
    int t = row & (Tt - 1);
    int tk = idx[row];
    const float* te = tok + (size_t)tk * Dm;
    const float* pe = pos + (size_t)t * Dm;
    float* xo = x + (size_t)row * Dm;
    for (int i = threadIdx.x; i < Dm; i += blockDim.x)
        xo[i] = te[i] + pe[i];
}

// ---------------- layernorm (output tf32-rounded: it only feeds gemm A) ------
__global__ void ln_kernel(const float* __restrict__ x,
                          const float* __restrict__ gs,
                          const float* __restrict__ gb,
                          float* __restrict__ out) {
    int row = blockIdx.x;
    int tid = threadIdx.x;
    const float* xr = x + (size_t)row * Dm;
    float* orow = out + (size_t)row * Dm;

    float v0 = xr[tid], v1 = xr[tid + 256], v2 = xr[tid + 512];
    float s = v0 + v1 + v2;
    __shared__ float red[8];
    #pragma unroll
    for (int o = 16; o; o >>= 1) s += __shfl_xor_sync(0xffffffffu, s, o);
    if ((tid & 31) == 0) red[tid >> 5] = s;
    __syncthreads();
    float mean = (red[0]+red[1]+red[2]+red[3]+red[4]+red[5]+red[6]+red[7]) * (1.0f / Dm);
    __syncthreads();

    float d0 = v0 - mean, d1 = v1 - mean, d2 = v2 - mean;
    float sq = d0*d0 + d1*d1 + d2*d2;
    #pragma unroll
    for (int o = 16; o; o >>= 1) sq += __shfl_xor_sync(0xffffffffu, sq, o);
    if ((tid & 31) == 0) red[tid >> 5] = sq;
    __syncthreads();
    float var = (red[0]+red[1]+red[2]+red[3]+red[4]+red[5]+red[6]+red[7]) * (1.0f / Dm);
    float rs = rsqrtf(var + EPSL);

    orow[tid]       = roundtf(d0 * rs * gs[tid]       + gb[tid]);
    orow[tid + 256] = roundtf(d1 * rs * gs[tid + 256] + gb[tid + 256]);
    orow[tid + 512] = roundtf(d2 * rs * gs[tid + 512] + gb[tid + 512]);
}

// ---------------- tf32 tensor-core GEMM --------------------------------------
__device__ __forceinline__ void mma_tf32(float* c, unsigned a0, unsigned a1,
                                         unsigned a2, unsigned a3,
                                         unsigned b0, unsigned b1) {
    asm volatile(
        "mma.sync.aligned.m16n8k8.row.col.f32.tf32.tf32.f32 "
        "{%0,%1,%2,%3}, {%4,%5,%6,%7}, {%8,%9}, {%0,%1,%2,%3};"
        : "+f"(c[0]), "+f"(c[1]), "+f"(c[2]), "+f"(c[3])
        : "r"(a0), "r"(a1), "r"(a2), "r"(a3), "r"(b0), "r"(b1));
}

// C = A[MxK] @ B[K x N, row stride ldB] (+bias)(+res)(relu)(roundC).
// A and B MUST be tf32-pre-rounded. B rows must be float4-aligned with
// n0+128 <= ldB for every block (all B operands come from padded scratch).
// blockIdx.z selects (B,C) among up to 3 weight/output pairs (QKV fusion).
// 128 threads, 4 warps in 2x2, warp tile 64x64.
__global__ __launch_bounds__(GT)
void gemm_tc(const float* __restrict__ A, const float* __restrict__ B,
             const float* __restrict__ bias, const float* __restrict__ res,
             float* __restrict__ C, int M, int N, int K, int ldB,
             int relu, int roundC,
             const float* B1, const float* B2, float* C1, float* C2) {
    if (blockIdx.z == 1) { B = B1; C = C1; }
    else if (blockIdx.z == 2) { B = B2; C = C2; }

    __shared__ __align__(16) unsigned Asm[2 * A_BUF];
    __shared__ __align__(16) unsigned Bsm[2 * B_BUF];

    int tid = threadIdx.x;
    int lane = tid & 31, wid = tid >> 5;
    int g = lane >> 2, tig = lane & 3;
    int wm = wid & 1, wn = wid >> 1;        // 2 x 2 warp grid, warp tile 64x64

    int m0 = blockIdx.x * BM, n0 = blockIdx.y * BN;

    // ---- fill-side indices ----
    // A: thread = row (0..127), loads all 16 k
    int amtile = tid >> 4, amt = tid & 15;
    int ahalf = amt >> 3, ag = amt & 7;
    unsigned a_st = amtile * 128 + ahalf * 2;          // + kb*A_KBLK + (ag*4+t)*4
    // B: thread = (krow 0..15, bn8 0..7) -> 16 consecutive n
    int bkrow = tid >> 3, bn8 = tid & 7;
    int bkb = bkrow >> 3, bkk = bkrow & 7;
    int bhi = bkk >> 2, btig = bkk & 3;
    unsigned b_st = bkb * B_KBLK + btig * 2 + bhi;     // + ntile*B_NT + gg*8

    const float* Aptr = A + (size_t)(m0 + tid) * K;
    const float* Bptr = B + (size_t)bkrow * ldB + n0 + bn8 * 16;

    float c[4][8][4] = {};
    float va[16], vb[16];

    // prologue: tile 0 -> buf 0
    #pragma unroll
    for (int u = 0; u < 4; u++) *(float4*)&va[u * 4] = *(const float4*)(Aptr + u * 4);
    #pragma unroll
    for (int u = 0; u < 4; u++) *(float4*)&vb[u * 4] = *(const float4*)(Bptr + u * 4);
    #pragma unroll
    for (int kb = 0; kb < 2; kb++)
        #pragma unroll
        for (int t = 0; t < 4; t++)
            *(uint2*)&Asm[kb * A_KBLK + a_st + (ag * 4 + t) * 4] =
                make_uint2(__float_as_uint(va[kb * 8 + t]),
                           __float_as_uint(va[kb * 8 + t + 4]));
    #pragma unroll
    for (int j = 0; j < 16; j++) {
        int ntile = bn8 * 2 + (j >> 3), gg = j & 7;
        Bsm[b_st + ntile * B_NT + gg * 8] = __float_as_uint(vb[j]);
    }
    __syncthreads();

    int nk = K / BK;
    for (int it = 0; it < nk; it++) {
        int buf = it & 1;
        bool more = (it + 1 < nk);
        if (more) {
            int k0 = (it + 1) * BK;
            #pragma unroll
            for (int u = 0; u < 4; u++)
                *(float4*)&va[u * 4] = *(const float4*)(Aptr + k0 + u * 4);
            #pragma unroll
            for (int u = 0; u < 4; u++)
                *(float4*)&vb[u * 4] = *(const float4*)(Bptr + (size_t)k0 * ldB + u * 4);
        }

        unsigned abuf = buf * A_BUF;
        unsigned bbuf = buf * B_BUF;
        #pragma unroll
        for (int ks8 = 0; ks8 < 2; ks8++) {
            uint4 av[4];
            uint2 bv[8];
            #pragma unroll
            for (int mi = 0; mi < 4; mi++)
                av[mi] = *(const uint4*)&Asm[abuf + ks8 * A_KBLK +
                                             (wm * 4 + mi) * 128 + lane * 4];
            #pragma unroll
            for (int ni = 0; ni < 8; ni++)
                bv[ni] = *(const uint2*)&Bsm[bbuf + ks8 * B_KBLK +
                                             (wn * 8 + ni) * B_NT + lane * 2];
            #pragma unroll
            for (int mi = 0; mi < 4; mi++)
                #pragma unroll
                for (int ni = 0; ni < 8; ni++)
                    mma_tf32(c[mi][ni], av[mi].x, av[mi].z, av[mi].y, av[mi].w,
                             bv[ni].x, bv[ni].y);
        }

        if (more) {
            unsigned nb = (buf ^ 1);
            unsigned an = nb * A_BUF, bn = nb * B_BUF;
            #pragma unroll
            for (int kb = 0; kb < 2; kb++)
                #pragma unroll
                for (int t = 0; t < 4; t++)
                    *(uint2*)&Asm[an + kb * A_KBLK + a_st + (ag * 4 + t) * 4] =
                        make_uint2(__float_as_uint(va[kb * 8 + t]),
                                   __float_as_uint(va[kb * 8 + t + 4]));
            #pragma unroll
            for (int j = 0; j < 16; j++) {
                int ntile = bn8 * 2 + (j >> 3), gg = j & 7;
                Bsm[bn + b_st + ntile * B_NT + gg * 8] = __float_as_uint(vb[j]);
            }
        }
        __syncthreads();
    }

    // epilogue: float2 stores only when every row offset stays 8B-aligned (N even)
    bool evenN = ((N & 1) == 0);
    #pragma unroll
    for (int mi = 0; mi < 4; mi++) {
        int r0 = m0 + wm * 64 + mi * 16 + g;
        #pragma unroll
        for (int ni = 0; ni < 8; ni++) {
            int col = n0 + wn * 64 + ni * 8 + 2 * tig;
            #pragma unroll
            for (int rr = 0; rr < 2; rr++) {
                int r = r0 + rr * 8;
                float v0 = c[mi][ni][rr * 2 + 0];
                float v1 = c[mi][ni][rr * 2 + 1];
                if (evenN && col + 1 < N) {
                    if (bias) { v0 += bias[col]; v1 += bias[col + 1]; }
                    if (res) {
                        float2 rv = *(const float2*)&res[(size_t)r * N + col];
                        v0 += rv.x; v1 += rv.y;
                    }
                    if (relu) { v0 = fmaxf(v0, 0.0f); v1 = fmaxf(v1, 0.0f); }
                    if (roundC) { v0 = roundtf(v0); v1 = roundtf(v1); }
                    float2 ov; ov.x = v0; ov.y = v1;
                    *(float2*)&C[(size_t)r * N + col] = ov;
                } else {
                    #pragma unroll
                    for (int cc = 0; cc < 2; cc++) {
                        int nn = col + cc;
                        if (nn < N) {
                            float v = (cc == 0) ? v0 : v1;
                            if (bias) v += bias[nn];
                            if (res)  v += res[(size_t)r * N + nn];
                            if (relu) v = fmaxf(v, 0.0f);
                            if (roundC) v = roundtf(v);
                            C[(size_t)r * N + nn] = v;
                        }
                    }
                }
            }
        }
    }
}

// ---------------- fused flash attention (fp32 SIMT, causal) -------------------
// grid (t_tile=16, bh=48), block 256, dynamic smem 4*64*FA_PAD floats
// output tf32-rounded (it only feeds the proj gemm A)
__global__ __launch_bounds__(256)
void flash_attn(const float* __restrict__ q, const float* __restrict__ k,
                const float* __restrict__ v, float* __restrict__ ao) {
    extern __shared__ float smf[];
    float* Qs = smf;                    // [64][FA_PAD]  Qs[d*FA_PAD + r] (transposed)
    float* Ks = smf + 64 * FA_PAD;      // Ks[d*FA_PAD + c]
    float* Vs = smf + 2 * 64 * FA_PAD;  // Vs[s*FA_PAD + j] (natural)
    float* Ps = smf + 3 * 64 * FA_PAD;  // Ps[s*FA_PAD + r] (transposed)

    int bh = blockIdx.y;
    int b = bh / Hn, h = bh % Hn;
    int tT = blockIdx.x;
    int t0 = tT * 64;

    int tid = threadIdx.x;
    int tx = tid & 15, ty = tid >> 4;
    int lr = tid >> 2;              // 0..63 (row for global loads)
    int lc0 = (tid & 3) * 16;       // 16 cols per loader thread

    // load Q tile (transposed, pre-scaled)
    {
        const float* qp = q + (size_t)(b * Tt + t0 + lr) * Dm + h * HS + lc0;
        #pragma unroll
        for (int u = 0; u < 4; u++) {
            float4 qv = *(const float4*)(qp + u * 4);
            Qs[(lc0 + u*4 + 0) * FA_PAD + lr] = qv.x * 0.125f;
            Qs[(lc0 + u*4 + 1) * FA_PAD + lr] = qv.y * 0.125f;
            Qs[(lc0 + u*4 + 2) * FA_PAD + lr] = qv.z * 0.125f;
            Qs[(lc0 + u*4 + 3) * FA_PAD + lr] = qv.w * 0.125f;
        }
    }

    float m[4], l[4], o[4][4];
    #pragma unroll
    for (int i = 0; i < 4; i++) {
        m[i] = -INFINITY; l[i] = 0.0f;
        #pragma unroll
        for (int j = 0; j < 4; j++) o[i][j] = 0.0f;
    }

    for (int st = 0; st <= tT; st++) {
        int s0 = st * 64;
        const float* kp = k + (size_t)(b * Tt + s0 + lr) * Dm + h * HS + lc0;
        const float* vp = v + (size_t)(b * Tt + s0 + lr) * Dm + h * HS + lc0;
        __syncthreads();
        #pragma unroll
        for (int u = 0; u < 4; u++) {
            float4 kv = *(const float4*)(kp + u * 4);
            Ks[(lc0 + u*4 + 0) * FA_PAD + lr] = kv.x;
            Ks[(lc0 + u*4 + 1) * FA_PAD + lr] = kv.y;
            Ks[(lc0 + u*4 + 2) * FA_PAD + lr] = kv.z;
            Ks[(lc0 + u*4 + 3) * FA_PAD + lr] = kv.w;
            float4 vv = *(const float4*)(vp + u * 4);
            *(float4*)&Vs[lr * FA_PAD + lc0 + u * 4] = vv;
        }
        __syncthreads();

        // S = Q K^T  (64x64)
        float sacc[4][4] = {};
        #pragma unroll 8
        for (int d = 0; d < 64; d++) {
            float4 a = *(const float4*)&Qs[d * FA_PAD + ty * 4];
            float4 bb = *(const float4*)&Ks[d * FA_PAD + tx * 4];
            float ra[4] = {a.x, a.y, a.z, a.w};
            float rb[4] = {bb.x, bb.y, bb.z, bb.w};
            #pragma unroll
            for (int i = 0; i < 4; i++)
                #pragma unroll
                for (int j = 0; j < 4; j++)
                    sacc[i][j] = fmaf(ra[i], rb[j], sacc[i][j]);
        }

        if (st == tT) {
            #pragma unroll
            for (int i = 0; i < 4; i++) {
                int t = t0 + ty * 4 + i;
                #pragma unroll
                for (int j = 0; j < 4; j++)
                    if (s0 + tx * 4 + j > t) sacc[i][j] = -INFINITY;
            }
        }

        // online softmax update per row (row group = 16 lanes in half-warp)
        #pragma unroll
        for (int i = 0; i < 4; i++) {
            float mx = fmaxf(fmaxf(sacc[i][0], sacc[i][1]),
                             fmaxf(sacc[i][2], sacc[i][3]));
            #pragma unroll
            for (int off = 8; off; off >>= 1)
                mx = fmaxf(mx, __shfl_xor_sync(0xffffffffu, mx, off));
            float mnew = fmaxf(m[i], mx);
            float alpha = __expf(m[i] - mnew);
            float rs = 0.0f;
            #pragma unroll
            for (int j = 0; j < 4; j++) {
                float p = __expf(sacc[i][j] - mnew);
                sacc[i][j] = p;
                rs += p;
            }
            #pragma unroll
            for (int off = 8; off; off >>= 1)
                rs += __shfl_xor_sync(0xffffffffu, rs, off);
            l[i] = l[i] * alpha + rs;
            m[i] = mnew;
            #pragma unroll
            for (int j = 0; j < 4; j++) {
                o[i][j] *= alpha;
                Ps[(tx * 4 + j) * FA_PAD + ty * 4 + i] = sacc[i][j];
            }
        }
        __syncthreads();

        // O += P V
        #pragma unroll 8
        for (int s = 0; s < 64; s++) {
            float4 a = *(const float4*)&Ps[s * FA_PAD + ty * 4];
            float4 bb = *(const float4*)&Vs[s * FA_PAD + tx * 4];
            float ra[4] = {a.x, a.y, a.z, a.w};
            float rb[4] = {bb.x, bb.y, bb.z, bb.w};
            #pragma unroll
            for (int i = 0; i < 4; i++)
                #pragma unroll
                for (int j = 0; j < 4; j++)
                    o[i][j] = fmaf(ra[i], rb[j], o[i][j]);
        }
    }

    #pragma unroll
    for (int i = 0; i < 4; i++) {
        float inv = 1.0f / l[i];
        float4 r;
        r.x = roundtf(o[i][0] * inv); r.y = roundtf(o[i][1] * inv);
        r.z = roundtf(o[i][2] * inv); r.w = roundtf(o[i][3] * inv);
        *(float4*)(ao + (size_t)(b * Tt + t0 + ty * 4 + i) * Dm + h * HS + tx * 4) = r;
    }
}

// ---------------- per-row NLL (online LSE, fast exp) --------------------------
__global__ void nll_kernel(const float* __restrict__ logits, const int* __restrict__ tgt,
                           float* __restrict__ nll) {
    int row = blockIdx.x;
    int tid = threadIdx.x;
    const float* lr = logits + (size_t)row * Vv;

    float m = -INFINITY, s = 0.0f;
    for (int i = tid; i < Vv; i += 256) {
        float x = lr[i];
        if (x > m) { s = s * __expf(m - x) + 1.0f; m = x; }
        else       { s += __expf(x - m); }
    }
    __shared__ float sm[256], ss[256];
    sm[tid] = m; ss[tid] = s;
    __syncthreads();
    for (int off = 128; off; off >>= 1) {
        if (tid < off) {
            float m2 = sm[tid + off], s2 = ss[tid + off];
            float mm = fmaxf(sm[tid], m2);
            ss[tid] = ss[tid] * __expf(sm[tid] - mm) + s2 * __expf(m2 - mm);
            sm[tid] = mm;
        }
        __syncthreads();
    }
    if (tid == 0) {
        float lse = sm[0] + logf(ss[0]);
        nll[row] = lse - lr[tgt[row]];
    }
}

__global__ void loss_reduce(const float* __restrict__ nll, float* __restrict__ out) {
    int tid = threadIdx.x;
    float s = 0.0f;
    for (int i = tid; i < MR; i += 256) s += nll[i];
    __shared__ float red[8];
    #pragma unroll
    for (int o = 16; o; o >>= 1) s += __shfl_xor_sync(0xffffffffu, s, o);
    if ((tid & 31) == 0) red[tid >> 5] = s;
    __syncthreads();
    if (tid == 0) {
        float tot = red[0]+red[1]+red[2]+red[3]+red[4]+red[5]+red[6]+red[7];
        out[0] = tot * (1.0f / MR);
    }
}

// ---------------- driver -----------------------------------------------------
extern "C" void kernel_launch(void* const* d_in, const int* in_sizes, int n_in,
                              void* d_out, int out_size) {
    const int*   idx   = (const int*)  d_in[0];
    const int*   tgt   = (const int*)  d_in[1];
    const float* tok   = (const float*)d_in[2];
    const float* pos   = (const float*)d_in[3];
    const float* ln1s  = (const float*)d_in[4];
    const float* ln1b  = (const float*)d_in[5];
    const float* Wq    = (const float*)d_in[6];
    const float* Wk    = (const float*)d_in[7];
    const float* Wv    = (const float*)d_in[8];
    const float* Wo    = (const float*)d_in[9];
    const float* bo    = (const float*)d_in[10];
    const float* ln2s  = (const float*)d_in[11];
    const float* ln2b  = (const float*)d_in[12];
    const float* W1    = (const float*)d_in[13];
    const float* b1    = (const float*)d_in[14];
    const float* W2    = (const float*)d_in[15];
    const float* b2    = (const float*)d_in[16];
    const float* lnfs  = (const float*)d_in[17];
    const float* lnfb  = (const float*)d_in[18];
    const float* lmW   = (const float*)d_in[19];
    const float* lmb   = (const float*)d_in[20];
    float* out = (float*)d_out;

    float *gx, *gh, *gq, *gk, *gv, *gao, *gmlp, *glmWp, *gnll;
    float *gwq, *gwk, *gwv, *gwo, *gw1, *gw2;
    cudaGetSymbolAddress((void**)&gx,    g_x);
    cudaGetSymbolAddress((void**)&gh,    g_h);
    cudaGetSymbolAddress((void**)&gq,    g_q);
    cudaGetSymbolAddress((void**)&gk,    g_k);
    cudaGetSymbolAddress((void**)&gv,    g_v);
    cudaGetSymbolAddress((void**)&gao,   g_ao);
    cudaGetSymbolAddress((void**)&gmlp,  g_mlp);
    cudaGetSymbolAddress((void**)&glmWp, g_lmWp);
    cudaGetSymbolAddress((void**)&gnll,  g_nll);
    cudaGetSymbolAddress((void**)&gwq,   g_wq);
    cudaGetSymbolAddress((void**)&gwk,   g_wk);
    cudaGetSymbolAddress((void**)&gwv,   g_wv);
    cudaGetSymbolAddress((void**)&gwo,   g_wo);
    cudaGetSymbolAddress((void**)&gw1,   g_w1);
    cudaGetSymbolAddress((void**)&gw2,   g_w2);

    const int FA_SMEM = 4 * 64 * FA_PAD * sizeof(float);   // ~69.6 KB
    cudaFuncSetAttribute(flash_attn, cudaFuncAttributeMaxDynamicSharedMemorySize, FA_SMEM);

    // ---- prep: tf32-round all weights into scratch (graph-captured, ~140us) --
    const size_t nDD = (size_t)Ln * Dm * Dm;
    const size_t nDF = (size_t)Ln * Dm * FF;
    round_copy<<<2048, 256>>>(Wq, gwq, nDD);
    round_copy<<<2048, 256>>>(Wk, gwk, nDD);
    round_copy<<<2048, 256>>>(Wv, gwv, nDD);
    round_copy<<<2048, 256>>>(Wo, gwo, nDD);
    round_copy<<<2048, 256>>>(W1, gw1, nDF);
    round_copy<<<2048, 256>>>(W2, gw2, nDF);
    pad_lmW<<<Dm, 256>>>(lmW, glmWp);

    embed_kernel<<<MR, 256>>>(idx, tok, pos, gx);

    dim3 gQKV(MR / BM, Dm / BN, 3);          // 32 x 6 x 3
    dim3 gDD (MR / BM, Dm / BN, 1);          // 32 x 6
    dim3 gF1 (MR / BM, FF / BN, 1);          // 32 x 24
    dim3 gFA(Tt / 64, Bb * Hn);              // 16 x 48

    for (int l = 0; l < Ln; l++) {
        const float* wq = gwq + (size_t)l * Dm * Dm;
        const float* wk = gwk + (size_t)l * Dm * Dm;
        const float* wv = gwv + (size_t)l * Dm * Dm;
        const float* wo = gwo + (size_t)l * Dm * Dm;
        const float* w1 = gw1 + (size_t)l * Dm * FF;
        const float* w2 = gw2 + (size_t)l * FF * Dm;

        ln_kernel<<<MR, 256>>>(gx, ln1s + l * Dm, ln1b + l * Dm, gh);
        gemm_tc<<<gQKV, GT>>>(gh, wq, nullptr, nullptr, gq, MR, Dm, Dm, Dm, 0, 0,
                              wk, wv, gk, gv);

        flash_attn<<<gFA, 256, FA_SMEM>>>(gq, gk, gv, gao);

        gemm_tc<<<gDD, GT>>>(gao, wo, bo + l * Dm, gx, gx, MR, Dm, Dm, Dm, 0, 0,
                             nullptr, nullptr, nullptr, nullptr);

        ln_kernel<<<MR, 256>>>(gx, ln2s + l * Dm, ln2b + l * Dm, gh);
        gemm_tc<<<gF1, GT>>>(gh, w1, b1 + (size_t)l * FF, nullptr, gmlp,
                             MR, FF, Dm, FF, 1, 1, nullptr, nullptr, nullptr, nullptr);
        gemm_tc<<<gDD, GT>>>(gmlp, w2, b2 + l * Dm, gx, gx, MR, Dm, FF, Dm, 0, 0,
                             nullptr, nullptr, nullptr, nullptr);
    }

    ln_kernel<<<MR, 256>>>(gx, lnfs, lnfb, gh);
    dim3 gV(MR / BM, NP / BN, 1);             // 32 x 393
    gemm_tc<<<gV, GT>>>(gh, glmWp, lmb, nullptr, out, MR, Vv, Dm, NP, 0, 0,
                        nullptr, nullptr, nullptr, nullptr);

    nll_kernel<<<MR, 256>>>(out, tgt, gnll);
    loss_reduce<<<1, 256>>>(gnll, out + (size_t)out_size - 1);
}